// round 1
// baseline (speedup 1.0000x reference)
#include <cuda_runtime.h>
#include <cstdint>

#define NMAX 4096
#define DDIM 1024
#define KTOP 32
#define THR 0.25f
#define SIMSTRIDE 4096

// ---------------- device scratch (static, allocation-free) ----------------
__device__ float g_sim[(size_t)NMAX * NMAX];      // 64 MB, pairwise sims (upper tri valid)
__device__ float g_Ec[(size_t)NMAX * DDIM];       // 16 MB, compacted embeddings
__device__ int g_idx[NMAX];                       // compact -> original index
__device__ int g_alive[NMAX];
__device__ unsigned long long g_topk[NMAX * KTOP];
__device__ int g_topfull[NMAX];
__device__ int g_partner[NMAX];
__device__ int g_m;
__device__ int g_done;
__device__ int g_occurred;

// ---------------- init: copy input -> out emb region, reset state ----------------
__global__ void k_init(const float* __restrict__ in, float* __restrict__ out) {
    size_t i = (size_t)blockIdx.x * blockDim.x + threadIdx.x;
    size_t total = (size_t)NMAX * DDIM;
    for (size_t p = i; p < total; p += (size_t)gridDim.x * blockDim.x) out[p] = in[p];
    if (i < NMAX) g_alive[i] = 1;
    if (i == 0) { g_done = 0; g_occurred = 0; g_m = NMAX; }
}

// ---------------- compact: order-preserving scan of alive -> g_idx, g_m ----------------
__global__ void k_compact() {
    __shared__ int wsum[32];
    __shared__ int wexcl[32];
    int t = threadIdx.x;              // 1024 threads
    int lane = t & 31, wid = t >> 5;
    int base = t * 4;
    int fl[4]; int cnt = 0;
#pragma unroll
    for (int q = 0; q < 4; q++) { fl[q] = g_alive[base + q]; cnt += fl[q]; }
    int inc = cnt;
#pragma unroll
    for (int off = 1; off < 32; off <<= 1) {
        int v = __shfl_up_sync(0xffffffffu, inc, off);
        if (lane >= off) inc += v;
    }
    if (lane == 31) wsum[wid] = inc;
    __syncthreads();
    if (wid == 0) {
        int v = wsum[lane];
        int iv = v;
#pragma unroll
        for (int off = 1; off < 32; off <<= 1) {
            int o = __shfl_up_sync(0xffffffffu, iv, off);
            if (lane >= off) iv += o;
        }
        wexcl[lane] = iv - v;
        if (lane == 31) g_m = iv;
    }
    __syncthreads();
    int excl = wexcl[wid] + (inc - cnt);
#pragma unroll
    for (int q = 0; q < 4; q++) {
        if (fl[q]) g_idx[excl++] = base + q;
    }
}

// ---------------- gather: Ec[b] = emb[idx[b]] ----------------
__global__ void k_gather(const float* __restrict__ emb) {
    if (g_done) return;
    int b = blockIdx.x;
    if (b >= g_m) return;
    const float4* src = (const float4*)(emb + (size_t)g_idx[b] * DDIM);
    float4* dst = (float4*)(g_Ec + (size_t)b * DDIM);
    dst[threadIdx.x] = src[threadIdx.x];
}

// ---------------- SGEMM: sim = Ec * Ec^T / D, upper-triangular tiles only ----------------
__global__ void __launch_bounds__(256) k_gemm() {
    if (g_done) return;
    int m = g_m;
    int bx = blockIdx.x, by = blockIdx.y;
    if (bx < by) return;                   // only tiles with some j >= i
    if (by * 128 >= m || bx * 128 >= m) return;

    __shared__ float As[16][132];
    __shared__ float Bs[16][132];

    int tid = threadIdx.x;
    int tx = tid & 15, ty = tid >> 4;
    int rowBase = by * 128, colBase = bx * 128;

    float acc[8][8];
#pragma unroll
    for (int r = 0; r < 8; r++)
#pragma unroll
        for (int c = 0; c < 8; c++) acc[r][c] = 0.0f;

    for (int k0 = 0; k0 < DDIM; k0 += 16) {
#pragma unroll
        for (int q = 0; q < 2; q++) {
            int v = tid * 2 + q;
            int ar = v >> 2;
            int k4 = (v & 3) * 4;
            float4 va = make_float4(0.f, 0.f, 0.f, 0.f);
            int gr = rowBase + ar;
            if (gr < m) va = *(const float4*)&g_Ec[(size_t)gr * DDIM + k0 + k4];
            As[k4 + 0][ar] = va.x; As[k4 + 1][ar] = va.y;
            As[k4 + 2][ar] = va.z; As[k4 + 3][ar] = va.w;
            float4 vb = make_float4(0.f, 0.f, 0.f, 0.f);
            int gc = colBase + ar;
            if (gc < m) vb = *(const float4*)&g_Ec[(size_t)gc * DDIM + k0 + k4];
            Bs[k4 + 0][ar] = vb.x; Bs[k4 + 1][ar] = vb.y;
            Bs[k4 + 2][ar] = vb.z; Bs[k4 + 3][ar] = vb.w;
        }
        __syncthreads();
#pragma unroll
        for (int kk = 0; kk < 16; kk++) {
            float ra[8], rb[8];
            *(float4*)&ra[0] = *(float4*)&As[kk][ty * 8];
            *(float4*)&ra[4] = *(float4*)&As[kk][ty * 8 + 4];
            *(float4*)&rb[0] = *(float4*)&Bs[kk][tx * 8];
            *(float4*)&rb[4] = *(float4*)&Bs[kk][tx * 8 + 4];
#pragma unroll
            for (int r = 0; r < 8; r++)
#pragma unroll
                for (int c = 0; c < 8; c++) acc[r][c] += ra[r] * rb[c];
        }
        __syncthreads();
    }

    const float inv = 1.0f / (float)DDIM;
#pragma unroll
    for (int r = 0; r < 8; r++) {
        int gi = rowBase + ty * 8 + r;
        if (gi >= m) continue;
        int gj0 = colBase + tx * 8;
        if (gj0 + 7 < m) {
            float4 v0, v1;
            v0.x = acc[r][0] * inv; v0.y = acc[r][1] * inv;
            v0.z = acc[r][2] * inv; v0.w = acc[r][3] * inv;
            v1.x = acc[r][4] * inv; v1.y = acc[r][5] * inv;
            v1.z = acc[r][6] * inv; v1.w = acc[r][7] * inv;
            *(float4*)&g_sim[(size_t)gi * SIMSTRIDE + gj0] = v0;
            *(float4*)&g_sim[(size_t)gi * SIMSTRIDE + gj0 + 4] = v1;
        } else {
#pragma unroll
            for (int c = 0; c < 8; c++) {
                int gj = gj0 + c;
                if (gj < m) g_sim[(size_t)gi * SIMSTRIDE + gj] = acc[r][c] * inv;
            }
        }
    }
}

// ---------------- top-K per row (threshold-filtered, sorted desc) ----------------
__global__ void __launch_bounds__(256) k_topk() {
    if (g_done) return;
    int i = blockIdx.x;
    int m = g_m;
    if (i >= m) return;
    int tid = threadIdx.x;
    int cnt = m - 1 - i;
    if (cnt <= 0) {
        if (tid < KTOP) g_topk[i * KTOP + tid] = 0ull;
        if (tid == 0) g_topfull[i] = 0;
        return;
    }

    __shared__ unsigned long long keys[NMAX];
    __shared__ unsigned long long tmax[256];
    __shared__ unsigned long long sel;
    __shared__ int selthr;

    const float* simrow = g_sim + (size_t)i * SIMSTRIDE;
    unsigned long long lmax = 0;
    for (int c = tid; c < cnt; c += 256) {
        int j = i + 1 + c;
        float s = simrow[j];
        unsigned long long key = 0;
        if (s >= THR)
            key = ((unsigned long long)__float_as_uint(s) << 32) |
                  (unsigned)(0xFFFFFFFFu - (unsigned)j);
        keys[c] = key;
        if (key > lmax) lmax = key;
    }
    tmax[tid] = lmax;
    __syncthreads();

    int found = 0;
    for (int it = 0; it < KTOP; it++) {
        if (tid < 32) {
            unsigned long long best = 0; int bt = 0;
#pragma unroll
            for (int q = 0; q < 8; q++) {
                unsigned long long v = tmax[tid * 8 + q];
                if (v > best) { best = v; bt = tid * 8 + q; }
            }
#pragma unroll
            for (int off = 16; off; off >>= 1) {
                unsigned long long ob = __shfl_down_sync(0xffffffffu, best, off);
                int obt = __shfl_down_sync(0xffffffffu, bt, off);
                if (ob > best) { best = ob; bt = obt; }
            }
            if (tid == 0) { sel = best; selthr = bt; }
        }
        __syncthreads();
        unsigned long long key = sel;
        if (key == 0ull) break;
        if (tid == 0) g_topk[i * KTOP + it] = key;
        if (tid == selthr) {
            unsigned long long nm = 0;
            for (int c = tid; c < cnt; c += 256) {
                if (keys[c] == key) keys[c] = 0ull;
                else if (keys[c] > nm) nm = keys[c];
            }
            tmax[tid] = nm;
        }
        found++;
        __syncthreads();
    }
    if (tid == 0) {
        g_topfull[i] = (found == KTOP) ? 1 : 0;
        for (int t2 = found; t2 < KTOP; t2++) g_topk[i * KTOP + t2] = 0ull;
    }
}

// ---------------- sequential greedy consumer (single block) ----------------
__global__ void __launch_bounds__(256) k_greedy() {
    if (g_done) return;
    __shared__ unsigned char s_merged[NMAX];
    __shared__ int s_cmd;
    __shared__ int s_j;
    __shared__ unsigned long long s_red[8];

    int tid = threadIdx.x;
    int lane = tid & 31, wid = tid >> 5;
    int m = g_m;
    for (int c = tid; c < NMAX; c += 256) s_merged[c] = 0;
    __syncthreads();

    int occurred = 0;
    // prefetch row 0's list into warp0 registers
    unsigned long long keyNext = 0;
    if (wid == 0 && m > 0) keyNext = g_topk[lane];

    for (int i = 0; i < m; i++) {
        if (wid == 0) {
            unsigned long long key = keyNext;
            if (i + 1 < m) keyNext = g_topk[(size_t)(i + 1) * KTOP + lane];
            int mi = s_merged[i];
            int j = 0;
            int valid = 0;
            if (!mi && key) {
                j = (int)(0xFFFFFFFFu - (unsigned)key);
                valid = (s_merged[j] == 0);
            }
            unsigned bal = __ballot_sync(0xffffffffu, valid);
            int cmd, jj = -1;
            if (bal) {
                int src = __ffs(bal) - 1;   // first (highest-key) valid entry
                jj = __shfl_sync(0xffffffffu, j, src);
                cmd = 1;
            } else if (!mi && g_topfull[i]) {
                cmd = 2;                    // all K consumed, list was full -> exact fallback
            } else {
                cmd = 0;
            }
            if (lane == 0) {
                s_cmd = cmd; s_j = jj;
                if (cmd == 1) {
                    s_merged[jj] = 1;
                    g_partner[i] = jj;
                    occurred = 1;
                } else if (cmd == 0) {
                    g_partner[i] = -1;
                }
            }
        }
        __syncthreads();
        if (s_cmd == 2) {
            const float* row = g_sim + (size_t)i * SIMSTRIDE;
            unsigned long long lmax = 0;
            for (int j = i + 1 + tid; j < m; j += 256) {
                float s = row[j];
                if (s >= THR && s_merged[j] == 0) {
                    unsigned long long k2 =
                        ((unsigned long long)__float_as_uint(s) << 32) |
                        (unsigned)(0xFFFFFFFFu - (unsigned)j);
                    if (k2 > lmax) lmax = k2;
                }
            }
#pragma unroll
            for (int off = 16; off; off >>= 1) {
                unsigned long long o = __shfl_down_sync(0xffffffffu, lmax, off);
                if (o > lmax) lmax = o;
            }
            if (lane == 0) s_red[wid] = lmax;
            __syncthreads();
            if (tid == 0) {
                unsigned long long best = 0;
#pragma unroll
                for (int w = 0; w < 8; w++) if (s_red[w] > best) best = s_red[w];
                if (best) {
                    int jj = (int)(0xFFFFFFFFu - (unsigned)best);
                    s_merged[jj] = 1;
                    g_partner[i] = jj;
                    occurred = 1;
                } else {
                    g_partner[i] = -1;
                }
            }
            __syncthreads();
        }
    }
    if (tid == 0) g_occurred = occurred;
}

// ---------------- apply merges ----------------
__global__ void k_apply(float* __restrict__ out) {
    if (g_done) return;
    int b = blockIdx.x;
    if (b >= g_m) return;
    int p = g_partner[b];
    if (p < 0) return;
    int oi = g_idx[b], op = g_idx[p];
    int tid = threadIdx.x;                 // 256 threads, float4 each
    float4* ri = (float4*)(out + (size_t)oi * DDIM);
    float4* rp = (float4*)(out + (size_t)op * DDIM);
    float4 a = ri[tid], bb = rp[tid];
    float4 f;
    f.x = fminf(a.x + bb.x, 1.0f);
    f.y = fminf(a.y + bb.y, 1.0f);
    f.z = fminf(a.z + bb.z, 1.0f);
    f.w = fminf(a.w + bb.w, 1.0f);
    ri[tid] = f;
    rp[tid] = make_float4(0.f, 0.f, 0.f, 0.f);
    if (tid == 0) g_alive[op] = 0;
}

// ---------------- finalize round: update done flag ----------------
__global__ void k_finalize() {
    __shared__ int s[8];
    int tid = threadIdx.x;
    int c = 0;
    for (int q = tid; q < NMAX; q += 256) c += g_alive[q];
#pragma unroll
    for (int off = 16; off; off >>= 1) c += __shfl_down_sync(0xffffffffu, c, off);
    if ((tid & 31) == 0) s[tid >> 5] = c;
    __syncthreads();
    if (tid == 0) {
        int tot = 0;
#pragma unroll
        for (int w = 0; w < 8; w++) tot += s[w];
        if (!g_done && (g_occurred == 0 || tot <= 1)) g_done = 1;
        g_occurred = 0;
    }
}

// ---------------- write alive mask as floats ----------------
__global__ void k_walive(float* __restrict__ out) {
    int t = blockIdx.x * blockDim.x + threadIdx.x;
    if (t < NMAX) out[(size_t)NMAX * DDIM + t] = g_alive[t] ? 1.0f : 0.0f;
}

// ---------------- launcher ----------------
extern "C" void kernel_launch(void* const* d_in, const int* in_sizes, int n_in,
                              void* d_out, int out_size) {
    const float* in = (const float*)d_in[0];
    float* out = (float*)d_out;
    (void)in_sizes; (void)n_in; (void)out_size;

    k_init<<<4096, 256>>>(in, out);
    for (int r = 0; r < 4; r++) {
        k_compact<<<1, 1024>>>();
        k_gather<<<NMAX, 256>>>(out);
        dim3 g(32, 32);
        k_gemm<<<g, 256>>>();
        k_topk<<<NMAX, 256>>>();
        k_greedy<<<1, 256>>>();
        k_apply<<<NMAX, 256>>>(out);
        k_finalize<<<1, 256>>>();
    }
    k_walive<<<16, 256>>>(out);
}